// round 4
// baseline (speedup 1.0000x reference)
#include <cuda_runtime.h>
#include <cstdint>

// NeighborSample: x (8,64,64,192) f32 -> out (8*64*64, 5, 5, 192) f32
// out[pix][i][j][k] = x[b][y+i-2][x+j-2][k] (zero-padded), pix = ((b*64)+y)*64+x
//
// Pure memory kernel. Flat float4 mapping: idx4 = ((pix*25 + ij)*48 + k4).
// Consecutive threads -> consecutive float4 -> fully coalesced loads & stores.

#define C4      48u          // 192 floats / 4
#define NPIX    32768u       // 8*64*64
#define N4      (NPIX * 25u * C4)   // 39,321,600 float4 elements

__global__ void __launch_bounds__(256) neighbor_sample_kernel(
    const float4* __restrict__ in, float4* __restrict__ out)
{
    unsigned idx = blockIdx.x * 256u + threadIdx.x;
    if (idx >= N4) return;

    // decode: idx = (pix*25 + ij)*48 + k4
    unsigned k4  = idx % C4;
    unsigned r   = idx / C4;
    unsigned ij  = r % 25u;
    unsigned pix = r / 25u;
    unsigned j   = ij % 5u;
    unsigned i   = ij / 5u;

    unsigned xcol = pix & 63u;
    unsigned yrow = (pix >> 6) & 63u;
    unsigned b    = pix >> 12;

    int sy = (int)(yrow + i) - 2;
    int sx = (int)(xcol + j) - 2;

    float4 v = make_float4(0.f, 0.f, 0.f, 0.f);
    if ((unsigned)sy < 64u && (unsigned)sx < 64u) {
        unsigned src = (((b << 6) + (unsigned)sy) << 6 | (unsigned)sx) * C4 + k4;
        v = __ldg(&in[src]);
    }
    // streaming store: output is write-once, keep the 25MB input resident in L2
    __stcs(&out[idx], v);
}

extern "C" void kernel_launch(void* const* d_in, const int* in_sizes, int n_in,
                              void* d_out, int out_size)
{
    const float4* in  = (const float4*)d_in[0];
    float4*       out = (float4*)d_out;
    unsigned blocks = (N4 + 255u) / 256u;   // 153,600 blocks
    neighbor_sample_kernel<<<blocks, 256>>>(in, out);
}